// round 6
// baseline (speedup 1.0000x reference)
#include <cuda_runtime.h>
#include <cuda_bf16.h>
#include <stdint.h>
#include <stddef.h>

#define DD 128
#define NMAX 50176
#define EMAX 409600

// ---------------- device scratch ----------------
__device__ float g_qa[NMAX * DD];
__device__ float g_qb[NMAX * DD];
__device__ float g_wtp[NMAX * DD];
__device__ float g_wxp[NMAX * DD];
__device__ __nv_bfloat16 g_ka16[NMAX * DD];
__device__ __nv_bfloat16 g_kb16[NMAX * DD];
__device__ int   g_deg[NMAX];
__device__ int   g_off[NMAX + 1];
__device__ int   g_cur[NMAX];
__device__ int   g_scol[EMAX];
__device__ int   g_bsum[64];

// ---------------- cp.async helpers (portable, Ampere+) ----------------
__device__ __forceinline__ void cp_async16(uint32_t dst_smem, const void* src, int src_sz) {
    asm volatile("cp.async.cg.shared.global [%0], [%1], 16, %2;" ::
                 "r"(dst_smem), "l"(src), "r"(src_sz) : "memory");
}
#define CP_ASYNC_COMMIT() asm volatile("cp.async.commit_group;" ::: "memory")
#define CP_ASYNC_WAIT_ALL() asm volatile("cp.async.wait_group 0;" ::: "memory")

// ---------------- tf32 warp MMA ----------------
__device__ __forceinline__ void mma_tf32(float* c, uint32_t a0, uint32_t a1,
                                         uint32_t a2, uint32_t a3,
                                         uint32_t b0, uint32_t b1) {
    asm volatile(
        "mma.sync.aligned.m16n8k8.row.col.f32.tf32.tf32.f32 "
        "{%0,%1,%2,%3}, {%4,%5,%6,%7}, {%8,%9}, {%0,%1,%2,%3};"
        : "+f"(c[0]), "+f"(c[1]), "+f"(c[2]), "+f"(c[3])
        : "r"(a0), "r"(a1), "r"(a2), "r"(a3), "r"(b0), "r"(b1));
}

__device__ __forceinline__ uint32_t f2tf32(float f) {
    uint32_t u;
    asm("cvt.rna.tf32.f32 %0, %1;" : "=r"(u) : "f"(f));
    return u;
}

// smem layout (floats): A[128][132], B0[128][132], B1[128][132]
#define ROWF 132
#define TILE_F (128 * ROWF)
#define SMEM_FLOATS (3 * TILE_F)

// ---------------- fused tf32 projection GEMM ----------------
// grid (ceil(N/128), 2). y=0: input t, weights {Qa,Ka,W_t}; y=1: x, {Qb,Kb,W_x}.
// D = A @ W^T (+bias). w==2 (message GEMM) uses 3xTF32 error compensation.
__global__ void __launch_bounds__(256, 1)
proj_mma_kernel(const float* __restrict__ x, const float* __restrict__ t,
                const float* __restrict__ Qa_w, const float* __restrict__ Ka_w,
                const float* __restrict__ W_t,
                const float* __restrict__ Qb_w, const float* __restrict__ Kb_w,
                const float* __restrict__ W_x,
                const float* __restrict__ Qa_b, const float* __restrict__ Ka_b,
                const float* __restrict__ Qb_b, const float* __restrict__ Kb_b, int N) {
    extern __shared__ float sm[];
    float* As = sm;
    float* Bs[2] = {sm + TILE_F, sm + 2 * TILE_F};
    uint32_t sm_base = (uint32_t)__cvta_generic_to_shared(sm);

    const int tid  = threadIdx.x;
    const int wid  = tid >> 5;
    const int lane = tid & 31;
    const int y    = blockIdx.y;
    const int row0 = blockIdx.x * 128;

    const float* in = y ? x : t;
    const float* Ws[3];
    const float* Bias[3];
    Ws[0] = y ? Qb_w : Qa_w;
    Ws[1] = y ? Kb_w : Ka_w;
    Ws[2] = y ? W_x : W_t;
    Bias[0] = y ? Qb_b : Qa_b;
    Bias[1] = y ? Kb_b : Ka_b;
    Bias[2] = nullptr;
    float* dst_q = y ? g_qb : g_qa;
    float* dst_w = y ? g_wxp : g_wtp;
    __nv_bfloat16* dst_k = y ? g_kb16 : g_ka16;

    // ---- initial async loads: A tile + B0 (weight 0) ----
#pragma unroll
    for (int it = 0; it < 16; it++) {
        int c = tid + it * 256;
        int r = c >> 5, q4 = c & 31;
        int gr = row0 + r;
        uint32_t dst = sm_base + (uint32_t)((r * ROWF + q4 * 4) * 4);
        cp_async16(dst, in + (size_t)gr * DD + q4 * 4, gr < N ? 16 : 0);
    }
#pragma unroll
    for (int it = 0; it < 16; it++) {
        int c = tid + it * 256;
        int r = c >> 5, q4 = c & 31;
        uint32_t dst = sm_base + (uint32_t)((TILE_F + r * ROWF + q4 * 4) * 4);
        cp_async16(dst, Ws[0] + (size_t)r * DD + q4 * 4, 16);
    }
    CP_ASYNC_COMMIT();
    CP_ASYNC_WAIT_ALL();
    __syncthreads();

    const int warpM = (wid >> 1) * 32;   // 0,32,64,96
    const int warpN = (wid & 1) * 64;    // 0,64
    const int g = lane >> 2;             // 0..7
    const int tg = lane & 3;             // 0..3

    for (int w = 0; w < 3; w++) {
        // prefetch next weight into the other buffer
        if (w < 2) {
            int nb = (w + 1) & 1;
            const float* Wn = Ws[w + 1];
#pragma unroll
            for (int it = 0; it < 16; it++) {
                int c = tid + it * 256;
                int r = c >> 5, q4 = c & 31;
                uint32_t dst = sm_base +
                    (uint32_t)(((1 + nb) * TILE_F + r * ROWF + q4 * 4) * 4);
                cp_async16(dst, Wn + (size_t)r * DD + q4 * 4, 16);
            }
            CP_ASYNC_COMMIT();
        }

        const float* Bw = Bs[w & 1];
        float acc[2][8][4];
#pragma unroll
        for (int fm = 0; fm < 2; fm++)
#pragma unroll
            for (int fn = 0; fn < 8; fn++)
#pragma unroll
                for (int i = 0; i < 4; i++) acc[fm][fn][i] = 0.f;

        const float* Ap = As + (warpM + g) * ROWF + tg;
        const float* Bp = Bw + (warpN + g) * ROWF + tg;

        if (w < 2) {
            // ---- plain single-pass tf32 (q/k path; score error tolerant) ----
#pragma unroll
            for (int ks = 0; ks < 16; ks++) {
                const int k = ks * 8;
                uint32_t a[2][4];
#pragma unroll
                for (int fm = 0; fm < 2; fm++) {
                    const float* ap = Ap + fm * 16 * ROWF + k;
                    a[fm][0] = __float_as_uint(ap[0]);
                    a[fm][1] = __float_as_uint(ap[8 * ROWF]);
                    a[fm][2] = __float_as_uint(ap[4]);
                    a[fm][3] = __float_as_uint(ap[8 * ROWF + 4]);
                }
#pragma unroll
                for (int fn = 0; fn < 8; fn++) {
                    const float* bp = Bp + fn * 8 * ROWF + k;
                    uint32_t b0 = __float_as_uint(bp[0]);
                    uint32_t b1 = __float_as_uint(bp[4]);
                    mma_tf32(acc[0][fn], a[0][0], a[0][1], a[0][2], a[0][3], b0, b1);
                    mma_tf32(acc[1][fn], a[1][0], a[1][1], a[1][2], a[1][3], b0, b1);
                }
            }
        } else {
            // ---- 3xTF32 compensated (message path; values hit the output) ----
#pragma unroll
            for (int ks = 0; ks < 16; ks++) {
                const int k = ks * 8;
                uint32_t ah[2][4], al[2][4];
#pragma unroll
                for (int fm = 0; fm < 2; fm++) {
                    const float* ap = Ap + fm * 16 * ROWF + k;
                    float v0 = ap[0], v1 = ap[8 * ROWF], v2 = ap[4], v3 = ap[8 * ROWF + 4];
                    ah[fm][0] = f2tf32(v0);
                    ah[fm][1] = f2tf32(v1);
                    ah[fm][2] = f2tf32(v2);
                    ah[fm][3] = f2tf32(v3);
                    al[fm][0] = __float_as_uint(v0 - __uint_as_float(ah[fm][0]));
                    al[fm][1] = __float_as_uint(v1 - __uint_as_float(ah[fm][1]));
                    al[fm][2] = __float_as_uint(v2 - __uint_as_float(ah[fm][2]));
                    al[fm][3] = __float_as_uint(v3 - __uint_as_float(ah[fm][3]));
                }
#pragma unroll
                for (int fn = 0; fn < 8; fn++) {
                    const float* bp = Bp + fn * 8 * ROWF + k;
                    float w0 = bp[0], w1 = bp[4];
                    uint32_t bh0 = f2tf32(w0), bh1 = f2tf32(w1);
                    uint32_t bl0 = __float_as_uint(w0 - __uint_as_float(bh0));
                    uint32_t bl1 = __float_as_uint(w1 - __uint_as_float(bh1));
#pragma unroll
                    for (int fm = 0; fm < 2; fm++) {
                        mma_tf32(acc[fm][fn], ah[fm][0], ah[fm][1], ah[fm][2], ah[fm][3],
                                 bh0, bh1);
                        mma_tf32(acc[fm][fn], al[fm][0], al[fm][1], al[fm][2], al[fm][3],
                                 bh0, bh1);
                        mma_tf32(acc[fm][fn], ah[fm][0], ah[fm][1], ah[fm][2], ah[fm][3],
                                 bl0, bl1);
                    }
                }
            }
        }

        // ---- epilogue ----
        const float* bias = Bias[w];
        float2 bv[8];
#pragma unroll
        for (int fn = 0; fn < 8; fn++) {
            int col = warpN + fn * 8 + 2 * tg;
            if (bias) bv[fn] = *(const float2*)(bias + col);
            else bv[fn] = make_float2(0.f, 0.f);
        }

#pragma unroll
        for (int fm = 0; fm < 2; fm++) {
            int m_lo = row0 + warpM + fm * 16 + g;
            int m_hi = m_lo + 8;
#pragma unroll
            for (int fn = 0; fn < 8; fn++) {
                int col = warpN + fn * 8 + 2 * tg;
                float o0 = acc[fm][fn][0] + bv[fn].x;
                float o1 = acc[fm][fn][1] + bv[fn].y;
                float o2 = acc[fm][fn][2] + bv[fn].x;
                float o3 = acc[fm][fn][3] + bv[fn].y;
                if (w == 1) {
                    if (m_lo < N) {
                        __nv_bfloat162 h = __floats2bfloat162_rn(o0, o1);
                        *(unsigned int*)(dst_k + (size_t)m_lo * DD + col) =
                            *(unsigned int*)&h;
                    }
                    if (m_hi < N) {
                        __nv_bfloat162 h = __floats2bfloat162_rn(o2, o3);
                        *(unsigned int*)(dst_k + (size_t)m_hi * DD + col) =
                            *(unsigned int*)&h;
                    }
                } else {
                    float* dst = (w == 0) ? dst_q : dst_w;
                    if (m_lo < N)
                        *(float2*)(dst + (size_t)m_lo * DD + col) = make_float2(o0, o1);
                    if (m_hi < N)
                        *(float2*)(dst + (size_t)m_hi * DD + col) = make_float2(o2, o3);
                }
            }
        }

        CP_ASYNC_WAIT_ALL();
        __syncthreads();
    }
}

// ---------------- CSR construction ----------------
__global__ void zero_deg_kernel(int N) {
    int i = blockIdx.x * blockDim.x + threadIdx.x;
    if (i < N) g_deg[i] = 0;
}

__global__ void count_deg_kernel(const int* __restrict__ rows, int E) {
    int e = blockIdx.x * blockDim.x + threadIdx.x;
    if (e < E) atomicAdd(&g_deg[rows[e]], 1);
}

// hierarchical scan: per-block local exclusive scan + block totals
__global__ void scan1_kernel(int N) {
    __shared__ int wsum[32];
    int tid = threadIdx.x, lane = tid & 31, wid = tid >> 5;
    int i = blockIdx.x * 1024 + tid;
    int v = (i < N) ? g_deg[i] : 0;
    int s = v;
#pragma unroll
    for (int off = 1; off < 32; off <<= 1) {
        int u = __shfl_up_sync(0xffffffffu, s, off);
        if (lane >= off) s += u;
    }
    if (lane == 31) wsum[wid] = s;
    __syncthreads();
    if (wid == 0) {
        int ts = wsum[lane];
#pragma unroll
        for (int off = 1; off < 32; off <<= 1) {
            int u = __shfl_up_sync(0xffffffffu, ts, off);
            if (lane >= off) ts += u;
        }
        wsum[lane] = ts;
    }
    __syncthreads();
    int excl = (wid > 0 ? wsum[wid - 1] : 0) + (s - v);
    if (i < N) g_off[i] = excl;
    if (tid == 1023) g_bsum[blockIdx.x] = wsum[31];
}

// warp-parallel exclusive scan of up to 64 block sums
__global__ void scan2_kernel(int G, int N, int E) {
    int lane = threadIdx.x;
    int v0 = (lane < G) ? g_bsum[lane] : 0;
    int v1 = (32 + lane < G) ? g_bsum[32 + lane] : 0;
    int s0 = v0;
#pragma unroll
    for (int off = 1; off < 32; off <<= 1) {
        int u = __shfl_up_sync(0xffffffffu, s0, off);
        if (lane >= off) s0 += u;
    }
    int t0 = __shfl_sync(0xffffffffu, s0, 31);
    int s1 = v1;
#pragma unroll
    for (int off = 1; off < 32; off <<= 1) {
        int u = __shfl_up_sync(0xffffffffu, s1, off);
        if (lane >= off) s1 += u;
    }
    s1 += t0;
    if (lane < G) g_bsum[lane] = s0 - v0;
    if (32 + lane < G) g_bsum[32 + lane] = s1 - v1;
    if (lane == 0) g_off[N] = E;
}

__global__ void scan3_kernel(int N) {
    int i = blockIdx.x * 1024 + threadIdx.x;
    if (i < N) {
        int o = g_off[i] + g_bsum[blockIdx.x];
        g_off[i] = o;
        g_cur[i] = o;
    }
}

__global__ void scatter_kernel(const int* __restrict__ rows, const int* __restrict__ cols,
                               int E) {
    int e = blockIdx.x * blockDim.x + threadIdx.x;
    if (e < E) {
        int p = atomicAdd(&g_cur[rows[e]], 1);
        g_scol[p] = cols[e];
    }
}

// ---------------- fused scores + aggregation: one warp per dest node ----------------
__global__ void agg_kernel(float* __restrict__ out_x, float* __restrict__ out_t, int N) {
    int w    = blockIdx.x * (blockDim.x >> 5) + (threadIdx.x >> 5);
    int lane = threadIdx.x & 31;
    if (w >= N) return;
    int p0 = g_off[w];
    int p1 = g_off[w + 1];

    const float s = 0.08838834764831845f;  // 1/sqrt(128)
    float4 qa = *(const float4*)(g_qa + (size_t)w * DD + lane * 4);
    float4 qb = *(const float4*)(g_qb + (size_t)w * DD + lane * 4);
    qa.x *= s; qa.y *= s; qa.z *= s; qa.w *= s;
    qb.x *= s; qb.y *= s; qb.z *= s; qb.w *= s;

    float stx = 0.f, sty = 0.f, stz = 0.f, stw = 0.f;
    float sxx = 0.f, sxy = 0.f, sxz = 0.f, sxw = 0.f;
    float da = 0.f, db = 0.f;

    int p = p0;
    for (; p + 1 < p1; p += 2) {
        int j0 = g_scol[p];
        int j1 = g_scol[p + 1];
        // issue all 8 gathers up front (max MLP)
        uint2 kau0 = *(const uint2*)(g_ka16 + (size_t)j0 * DD + lane * 4);
        uint2 kbu0 = *(const uint2*)(g_kb16 + (size_t)j0 * DD + lane * 4);
        float4 wt0 = *(const float4*)(g_wtp + (size_t)j0 * DD + lane * 4);
        float4 wx0 = *(const float4*)(g_wxp + (size_t)j0 * DD + lane * 4);
        uint2 kau1 = *(const uint2*)(g_ka16 + (size_t)j1 * DD + lane * 4);
        uint2 kbu1 = *(const uint2*)(g_kb16 + (size_t)j1 * DD + lane * 4);
        float4 wt1 = *(const float4*)(g_wtp + (size_t)j1 * DD + lane * 4);
        float4 wx1 = *(const float4*)(g_wxp + (size_t)j1 * DD + lane * 4);

        float2 a00 = __bfloat1622float2(*(__nv_bfloat162*)&kau0.x);
        float2 a01 = __bfloat1622float2(*(__nv_bfloat162*)&kau0.y);
        float2 b00 = __bfloat1622float2(*(__nv_bfloat162*)&kbu0.x);
        float2 b01 = __bfloat1622float2(*(__nv_bfloat162*)&kbu0.y);
        float2 a10 = __bfloat1622float2(*(__nv_bfloat162*)&kau1.x);
        float2 a11 = __bfloat1622float2(*(__nv_bfloat162*)&kau1.y);
        float2 b10 = __bfloat1622float2(*(__nv_bfloat162*)&kbu1.x);
        float2 b11 = __bfloat1622float2(*(__nv_bfloat162*)&kbu1.y);

        float sa0 = qa.x * a00.x + qa.y * a00.y + qa.z * a01.x + qa.w * a01.y;
        float sb0 = qb.x * b00.x + qb.y * b00.y + qb.z * b01.x + qb.w * b01.y;
        float sa1 = qa.x * a10.x + qa.y * a10.y + qa.z * a11.x + qa.w * a11.y;
        float sb1 = qb.x * b10.x + qb.y * b10.y + qb.z * b11.x + qb.w * b11.y;
#pragma unroll
        for (int off = 16; off > 0; off >>= 1) {
            sa0 += __shfl_xor_sync(0xffffffffu, sa0, off);
            sb0 += __shfl_xor_sync(0xffffffffu, sb0, off);
            sa1 += __shfl_xor_sync(0xffffffffu, sa1, off);
            sb1 += __shfl_xor_sync(0xffffffffu, sb1, off);
        }
        float ea0 = __expf(sa0), eb0 = __expf(sb0);
        float ea1 = __expf(sa1), eb1 = __expf(sb1);

        stx = fmaf(ea0, wt0.x, fmaf(ea1, wt1.x, stx));
        sty = fmaf(ea0, wt0.y, fmaf(ea1, wt1.y, sty));
        stz = fmaf(ea0, wt0.z, fmaf(ea1, wt1.z, stz));
        stw = fmaf(ea0, wt0.w, fmaf(ea1, wt1.w, stw));
        sxx = fmaf(eb0, wx0.x, fmaf(eb1, wx1.x, sxx));
        sxy = fmaf(eb0, wx0.y, fmaf(eb1, wx1.y, sxy));
        sxz = fmaf(eb0, wx0.z, fmaf(eb1, wx1.z, sxz));
        sxw = fmaf(eb0, wx0.w, fmaf(eb1, wx1.w, sxw));
        da += ea0 + ea1;
        db += eb0 + eb1;
    }
    if (p < p1) {
        int j = g_scol[p];
        uint2 kau = *(const uint2*)(g_ka16 + (size_t)j * DD + lane * 4);
        uint2 kbu = *(const uint2*)(g_kb16 + (size_t)j * DD + lane * 4);
        float4 wt = *(const float4*)(g_wtp + (size_t)j * DD + lane * 4);
        float4 wx = *(const float4*)(g_wxp + (size_t)j * DD + lane * 4);

        float2 ka0 = __bfloat1622float2(*(__nv_bfloat162*)&kau.x);
        float2 ka1 = __bfloat1622float2(*(__nv_bfloat162*)&kau.y);
        float2 kb0 = __bfloat1622float2(*(__nv_bfloat162*)&kbu.x);
        float2 kb1 = __bfloat1622float2(*(__nv_bfloat162*)&kbu.y);

        float sa = qa.x * ka0.x + qa.y * ka0.y + qa.z * ka1.x + qa.w * ka1.y;
        float sb = qb.x * kb0.x + qb.y * kb0.y + qb.z * kb1.x + qb.w * kb1.y;
#pragma unroll
        for (int off = 16; off > 0; off >>= 1) {
            sa += __shfl_xor_sync(0xffffffffu, sa, off);
            sb += __shfl_xor_sync(0xffffffffu, sb, off);
        }
        float ea = __expf(sa), eb = __expf(sb);
        stx = fmaf(ea, wt.x, stx);
        sty = fmaf(ea, wt.y, sty);
        stz = fmaf(ea, wt.z, stz);
        stw = fmaf(ea, wt.w, stw);
        sxx = fmaf(eb, wx.x, sxx);
        sxy = fmaf(eb, wx.y, sxy);
        sxz = fmaf(eb, wx.z, sxz);
        sxw = fmaf(eb, wx.w, sxw);
        da += ea;
        db += eb;
    }
    float ia = (da > 0.f) ? 1.f / da : 0.f;
    float ib = (db > 0.f) ? 1.f / db : 0.f;
    *(float4*)(out_t + (size_t)w * DD + lane * 4) =
        make_float4(stx * ia, sty * ia, stz * ia, stw * ia);
    *(float4*)(out_x + (size_t)w * DD + lane * 4) =
        make_float4(sxx * ib, sxy * ib, sxz * ib, sxw * ib);
}

// ---------------- launch ----------------
extern "C" void kernel_launch(void* const* d_in, const int* in_sizes, int n_in,
                              void* d_out, int out_size) {
    const float* x    = (const float*)d_in[0];
    const float* t    = (const float*)d_in[1];
    const int*   ei   = (const int*)d_in[2];
    const float* W_x  = (const float*)d_in[3];
    const float* W_t  = (const float*)d_in[4];
    const float* Qa_w = (const float*)d_in[5];
    const float* Qa_b = (const float*)d_in[6];
    const float* Ka_w = (const float*)d_in[7];
    const float* Ka_b = (const float*)d_in[8];
    const float* Qb_w = (const float*)d_in[9];
    const float* Qb_b = (const float*)d_in[10];
    const float* Kb_w = (const float*)d_in[11];
    const float* Kb_b = (const float*)d_in[12];

    const int N = in_sizes[0] / DD;
    const int E = in_sizes[2] / 2;
    const int* rows = ei;
    const int* cols = ei + E;

    float* out_x = (float*)d_out;
    float* out_t = out_x + (size_t)N * DD;

    // CSR
    zero_deg_kernel<<<(N + 255) / 256, 256>>>(N);
    count_deg_kernel<<<(E + 255) / 256, 256>>>(rows, E);
    const int G = (N + 1023) / 1024;
    scan1_kernel<<<G, 1024>>>(N);
    scan2_kernel<<<1, 32>>>(G, N, E);
    scan3_kernel<<<G, 1024>>>(N);
    scatter_kernel<<<(E + 255) / 256, 256>>>(rows, cols, E);

    // projections via warp-level tf32 mma (message GEMM 3xTF32-compensated)
    const int smem = SMEM_FLOATS * (int)sizeof(float);
    cudaFuncSetAttribute(proj_mma_kernel, cudaFuncAttributeMaxDynamicSharedMemorySize,
                         smem);
    dim3 pg((N + 127) / 128, 2);
    proj_mma_kernel<<<pg, 256, smem>>>(x, t, Qa_w, Ka_w, W_t, Qb_w, Kb_w, W_x,
                                       Qa_b, Ka_b, Qb_b, Kb_b, N);

    agg_kernel<<<(N + 7) / 8, 256>>>(out_x, out_t, N);
}

// round 7
// speedup vs baseline: 1.1456x; 1.1456x over previous
#include <cuda_runtime.h>
#include <cuda_bf16.h>
#include <stdint.h>
#include <stddef.h>

#define DD 128
#define NMAX 50176
#define EMAX 409600

// ---------------- device scratch ----------------
__device__ float g_qa[NMAX * DD];
__device__ float g_qb[NMAX * DD];
__device__ float g_wtp[NMAX * DD];
__device__ float g_wxp[NMAX * DD];
__device__ __nv_bfloat16 g_ka16[NMAX * DD];
__device__ __nv_bfloat16 g_kb16[NMAX * DD];
__device__ __nv_bfloat16 g_wb16[6 * DD * DD];   // bf16-rounded weights
__device__ __nv_bfloat16 g_wl16[2 * DD * DD];   // bf16 residuals for W_t, W_x
__device__ int   g_deg[NMAX];
__device__ int   g_off[NMAX + 1];
__device__ int   g_cur[NMAX];
__device__ int   g_scol[EMAX];
__device__ int   g_bsum[64];

// ---------------- cp.async helpers (portable, Ampere+) ----------------
__device__ __forceinline__ void cp_async16(uint32_t dst_smem, const void* src) {
    asm volatile("cp.async.cg.shared.global [%0], [%1], 16;" ::
                 "r"(dst_smem), "l"(src) : "memory");
}
#define CP_ASYNC_COMMIT() asm volatile("cp.async.commit_group;" ::: "memory")
#define CP_ASYNC_WAIT_ALL() asm volatile("cp.async.wait_group 0;" ::: "memory")

// ---------------- bf16 warp MMA (m16n8k16) ----------------
__device__ __forceinline__ void mma_bf16(float* c, uint32_t a0, uint32_t a1,
                                         uint32_t a2, uint32_t a3,
                                         uint32_t b0, uint32_t b1) {
    asm volatile(
        "mma.sync.aligned.m16n8k16.row.col.f32.bf16.bf16.f32 "
        "{%0,%1,%2,%3}, {%4,%5,%6,%7}, {%8,%9}, {%0,%1,%2,%3};"
        : "+f"(c[0]), "+f"(c[1]), "+f"(c[2]), "+f"(c[3])
        : "r"(a0), "r"(a1), "r"(a2), "r"(a3), "r"(b0), "r"(b1));
}

// smem layout (bf16 elems): Ah[64][136], Al[64][136], B0[128][136], B1[128][136]
#define ROWE 136
#define AH_OFF 0
#define AL_OFF (64 * ROWE)
#define B0_OFF (2 * 64 * ROWE)
#define B1_OFF (B0_OFF + 128 * ROWE)
#define SMEM_ELEMS (B1_OFF + 128 * ROWE)
#define SMEM_BYTES (SMEM_ELEMS * 2)

// ---------------- weight round/split kernel ----------------
__global__ void wsplit_kernel(const float* __restrict__ W0, const float* __restrict__ W1,
                              const float* __restrict__ W2, const float* __restrict__ W3,
                              const float* __restrict__ W4, const float* __restrict__ W5) {
    const float* W;
    switch (blockIdx.x) {
        case 0: W = W0; break;
        case 1: W = W1; break;
        case 2: W = W2; break;
        case 3: W = W3; break;
        case 4: W = W4; break;
        default: W = W5; break;
    }
    __nv_bfloat16* dst = g_wb16 + blockIdx.x * (DD * DD);
    int resid = (blockIdx.x == 2) ? 0 : ((blockIdx.x == 5) ? 1 : -1);
    for (int i = threadIdx.x; i < DD * DD; i += 256) {
        float v = W[i];
        __nv_bfloat16 h = __float2bfloat16_rn(v);
        dst[i] = h;
        if (resid >= 0)
            g_wl16[resid * (DD * DD) + i] =
                __float2bfloat16_rn(v - __bfloat162float(h));
    }
}

// ---------------- GEMM inner pass: acc += A(16 rows) @ B(64 cols)^T ----------------
__device__ __forceinline__ void gemm_pass(float acc[8][4], const __nv_bfloat16* Abase,
                                          const __nv_bfloat16* Bbase, int warpM,
                                          int warpN, int g, int tg) {
    const __nv_bfloat16* Ap = Abase + (warpM + g) * ROWE + 2 * tg;
    const __nv_bfloat16* Bp = Bbase + (warpN + g) * ROWE + 2 * tg;
#pragma unroll
    for (int ks = 0; ks < 8; ks++) {
        const int k0 = ks * 16;
        uint32_t a0 = *(const uint32_t*)(Ap + k0);
        uint32_t a1 = *(const uint32_t*)(Ap + 8 * ROWE + k0);
        uint32_t a2 = *(const uint32_t*)(Ap + k0 + 8);
        uint32_t a3 = *(const uint32_t*)(Ap + 8 * ROWE + k0 + 8);
#pragma unroll
        for (int fn = 0; fn < 8; fn++) {
            const __nv_bfloat16* bp = Bp + fn * 8 * ROWE + k0;
            uint32_t b0 = *(const uint32_t*)bp;
            uint32_t b1 = *(const uint32_t*)(bp + 8);
            mma_bf16(acc[fn], a0, a1, a2, a3, b0, b1);
        }
    }
}

// ---------------- fused bf16 projection GEMM ----------------
// grid (ceil(N/64), 2). y=0: input t -> {qa, ka16, wtp}; y=1: x -> {qb, kb16, wxp}.
// D = A @ W^T (+bias). Message GEMM (w==2) uses bf16x2 split: Ah*Wh + Al*Wh + Ah*Wl.
__global__ void __launch_bounds__(256, 2)
proj_mma_kernel(const float* __restrict__ x, const float* __restrict__ t,
                const float* __restrict__ Qa_b, const float* __restrict__ Ka_b,
                const float* __restrict__ Qb_b, const float* __restrict__ Kb_b, int N) {
    extern __shared__ __nv_bfloat16 sm[];
    uint32_t sm_base = (uint32_t)__cvta_generic_to_shared(sm);

    const int tid  = threadIdx.x;
    const int wid  = tid >> 5;
    const int lane = tid & 31;
    const int y    = blockIdx.y;
    const int row0 = blockIdx.x * 64;

    const float* in = y ? x : t;
    const float* Bias[2];
    Bias[0] = y ? Qb_b : Qa_b;
    Bias[1] = y ? Kb_b : Ka_b;
    float* dst_q = y ? g_qb : g_qa;
    float* dst_w = y ? g_wxp : g_wtp;
    __nv_bfloat16* dst_k = y ? g_kb16 : g_ka16;
    const __nv_bfloat16* wb = g_wb16 + (size_t)(y * 3) * (DD * DD);
    const __nv_bfloat16* wl = g_wl16 + (size_t)y * (DD * DD);

    // ---- issue B0 <- W[0] (bf16 tile, 128 rows x 256B = 2048 x 16B chunks) ----
#pragma unroll
    for (int it = 0; it < 8; it++) {
        int c = tid + it * 256;
        int r = c >> 4, h8 = c & 15;  // 16 chunks of 8 elems per row
        uint32_t dst = sm_base + (uint32_t)((B0_OFF + r * ROWE + h8 * 8) * 2);
        cp_async16(dst, wb + (size_t)r * DD + h8 * 8);
    }
    CP_ASYNC_COMMIT();

    // ---- load A tile (64 x 128 fp32), split into Ah/Al bf16 ----
#pragma unroll
    for (int it = 0; it < 8; it++) {
        int c = tid + it * 256;
        int r = c >> 5, q4 = c & 31;
        int gr = row0 + r;
        float4 v = make_float4(0.f, 0.f, 0.f, 0.f);
        if (gr < N) v = *(const float4*)(in + (size_t)gr * DD + q4 * 4);
        __nv_bfloat16 h0 = __float2bfloat16_rn(v.x);
        __nv_bfloat16 h1 = __float2bfloat16_rn(v.y);
        __nv_bfloat16 h2 = __float2bfloat16_rn(v.z);
        __nv_bfloat16 h3 = __float2bfloat16_rn(v.w);
        __nv_bfloat16 l0 = __float2bfloat16_rn(v.x - __bfloat162float(h0));
        __nv_bfloat16 l1 = __float2bfloat16_rn(v.y - __bfloat162float(h1));
        __nv_bfloat16 l2 = __float2bfloat16_rn(v.z - __bfloat162float(h2));
        __nv_bfloat16 l3 = __float2bfloat16_rn(v.w - __bfloat162float(h3));
        __nv_bfloat16* ah = sm + AH_OFF + r * ROWE + q4 * 4;
        __nv_bfloat16* al = sm + AL_OFF + r * ROWE + q4 * 4;
        ah[0] = h0; ah[1] = h1; ah[2] = h2; ah[3] = h3;
        al[0] = l0; al[1] = l1; al[2] = l2; al[3] = l3;
    }
    CP_ASYNC_WAIT_ALL();
    __syncthreads();

    const int warpM = (wid >> 1) * 16;   // 0,16,32,48
    const int warpN = (wid & 1) * 64;    // 0,64
    const int g = lane >> 2;             // 0..7
    const int tg = lane & 3;             // 0..3
    const __nv_bfloat16* Ahs = sm + AH_OFF;
    const __nv_bfloat16* Als = sm + AL_OFF;
    const __nv_bfloat16* Bs0 = sm + B0_OFF;
    const __nv_bfloat16* Bs1 = sm + B1_OFF;

    // ---- prefetch B1 <- W[1], compute w0 on B0 ----
#pragma unroll
    for (int it = 0; it < 8; it++) {
        int c = tid + it * 256;
        int r = c >> 4, h8 = c & 15;
        uint32_t dst = sm_base + (uint32_t)((B1_OFF + r * ROWE + h8 * 8) * 2);
        cp_async16(dst, wb + (size_t)DD * DD + (size_t)r * DD + h8 * 8);
    }
    CP_ASYNC_COMMIT();

    float acc[8][4];
#pragma unroll
    for (int fn = 0; fn < 8; fn++)
#pragma unroll
        for (int i = 0; i < 4; i++) acc[fn][i] = 0.f;
    gemm_pass(acc, Ahs, Bs0, warpM, warpN, g, tg);

    // epilogue w0 -> q (fp32 + bias)
    {
        const float* bias = Bias[0];
        int m_lo = row0 + warpM + g, m_hi = m_lo + 8;
#pragma unroll
        for (int fn = 0; fn < 8; fn++) {
            int col = warpN + fn * 8 + 2 * tg;
            float2 bv = *(const float2*)(bias + col);
            if (m_lo < N)
                *(float2*)(dst_q + (size_t)m_lo * DD + col) =
                    make_float2(acc[fn][0] + bv.x, acc[fn][1] + bv.y);
            if (m_hi < N)
                *(float2*)(dst_q + (size_t)m_hi * DD + col) =
                    make_float2(acc[fn][2] + bv.x, acc[fn][3] + bv.y);
        }
    }
    CP_ASYNC_WAIT_ALL();
    __syncthreads();

    // ---- prefetch B0 <- W[2] hi (Wh), compute w1 on B1 ----
#pragma unroll
    for (int it = 0; it < 8; it++) {
        int c = tid + it * 256;
        int r = c >> 4, h8 = c & 15;
        uint32_t dst = sm_base + (uint32_t)((B0_OFF + r * ROWE + h8 * 8) * 2);
        cp_async16(dst, wb + (size_t)2 * DD * DD + (size_t)r * DD + h8 * 8);
    }
    CP_ASYNC_COMMIT();

#pragma unroll
    for (int fn = 0; fn < 8; fn++)
#pragma unroll
        for (int i = 0; i < 4; i++) acc[fn][i] = 0.f;
    gemm_pass(acc, Ahs, Bs1, warpM, warpN, g, tg);

    // epilogue w1 -> k (bf16 + bias)
    {
        const float* bias = Bias[1];
        int m_lo = row0 + warpM + g, m_hi = m_lo + 8;
#pragma unroll
        for (int fn = 0; fn < 8; fn++) {
            int col = warpN + fn * 8 + 2 * tg;
            float2 bv = *(const float2*)(bias + col);
            if (m_lo < N) {
                __nv_bfloat162 h = __floats2bfloat162_rn(acc[fn][0] + bv.x,
                                                         acc[fn][1] + bv.y);
                *(unsigned int*)(dst_k + (size_t)m_lo * DD + col) = *(unsigned int*)&h;
            }
            if (m_hi < N) {
                __nv_bfloat162 h = __floats2bfloat162_rn(acc[fn][2] + bv.x,
                                                         acc[fn][3] + bv.y);
                *(unsigned int*)(dst_k + (size_t)m_hi * DD + col) = *(unsigned int*)&h;
            }
        }
    }
    CP_ASYNC_WAIT_ALL();
    __syncthreads();

    // ---- prefetch B1 <- Wl, compute w2 passes 1+2 on B0 (Wh) ----
#pragma unroll
    for (int it = 0; it < 8; it++) {
        int c = tid + it * 256;
        int r = c >> 4, h8 = c & 15;
        uint32_t dst = sm_base + (uint32_t)((B1_OFF + r * ROWE + h8 * 8) * 2);
        cp_async16(dst, wl + (size_t)r * DD + h8 * 8);
    }
    CP_ASYNC_COMMIT();

#pragma unroll
    for (int fn = 0; fn < 8; fn++)
#pragma unroll
        for (int i = 0; i < 4; i++) acc[fn][i] = 0.f;
    gemm_pass(acc, Ahs, Bs0, warpM, warpN, g, tg);   // Ah * Wh
    gemm_pass(acc, Als, Bs0, warpM, warpN, g, tg);   // Al * Wh
    CP_ASYNC_WAIT_ALL();
    __syncthreads();
    gemm_pass(acc, Ahs, Bs1, warpM, warpN, g, tg);   // Ah * Wl

    // epilogue w2 -> message (fp32, no bias)
    {
        int m_lo = row0 + warpM + g, m_hi = m_lo + 8;
#pragma unroll
        for (int fn = 0; fn < 8; fn++) {
            int col = warpN + fn * 8 + 2 * tg;
            if (m_lo < N)
                *(float2*)(dst_w + (size_t)m_lo * DD + col) =
                    make_float2(acc[fn][0], acc[fn][1]);
            if (m_hi < N)
                *(float2*)(dst_w + (size_t)m_hi * DD + col) =
                    make_float2(acc[fn][2], acc[fn][3]);
        }
    }
}

// ---------------- CSR construction ----------------
__global__ void zero_deg_kernel(int N) {
    int i = blockIdx.x * blockDim.x + threadIdx.x;
    if (i < N) g_deg[i] = 0;
}

__global__ void count_deg_kernel(const int* __restrict__ rows, int E) {
    int e = blockIdx.x * blockDim.x + threadIdx.x;
    if (e < E) atomicAdd(&g_deg[rows[e]], 1);
}

__global__ void scan1_kernel(int N) {
    __shared__ int wsum[32];
    int tid = threadIdx.x, lane = tid & 31, wid = tid >> 5;
    int i = blockIdx.x * 1024 + tid;
    int v = (i < N) ? g_deg[i] : 0;
    int s = v;
#pragma unroll
    for (int off = 1; off < 32; off <<= 1) {
        int u = __shfl_up_sync(0xffffffffu, s, off);
        if (lane >= off) s += u;
    }
    if (lane == 31) wsum[wid] = s;
    __syncthreads();
    if (wid == 0) {
        int ts = wsum[lane];
#pragma unroll
        for (int off = 1; off < 32; off <<= 1) {
            int u = __shfl_up_sync(0xffffffffu, ts, off);
            if (lane >= off) ts += u;
        }
        wsum[lane] = ts;
    }
    __syncthreads();
    int excl = (wid > 0 ? wsum[wid - 1] : 0) + (s - v);
    if (i < N) g_off[i] = excl;
    if (tid == 1023) g_bsum[blockIdx.x] = wsum[31];
}

__global__ void scan2_kernel(int G, int N, int E) {
    int lane = threadIdx.x;
    int v0 = (lane < G) ? g_bsum[lane] : 0;
    int v1 = (32 + lane < G) ? g_bsum[32 + lane] : 0;
    int s0 = v0;
#pragma unroll
    for (int off = 1; off < 32; off <<= 1) {
        int u = __shfl_up_sync(0xffffffffu, s0, off);
        if (lane >= off) s0 += u;
    }
    int t0 = __shfl_sync(0xffffffffu, s0, 31);
    int s1 = v1;
#pragma unroll
    for (int off = 1; off < 32; off <<= 1) {
        int u = __shfl_up_sync(0xffffffffu, s1, off);
        if (lane >= off) s1 += u;
    }
    s1 += t0;
    if (lane < G) g_bsum[lane] = s0 - v0;
    if (32 + lane < G) g_bsum[32 + lane] = s1 - v1;
    if (lane == 0) g_off[N] = E;
}

__global__ void scan3_kernel(int N) {
    int i = blockIdx.x * 1024 + threadIdx.x;
    if (i < N) {
        int o = g_off[i] + g_bsum[blockIdx.x];
        g_off[i] = o;
        g_cur[i] = o;
    }
}

__global__ void scatter_kernel(const int* __restrict__ rows, const int* __restrict__ cols,
                               int E) {
    int e = blockIdx.x * blockDim.x + threadIdx.x;
    if (e < E) {
        int p = atomicAdd(&g_cur[rows[e]], 1);
        g_scol[p] = cols[e];
    }
}

// ---------------- fused scores + aggregation: one warp per dest node ----------------
__global__ void agg_kernel(float* __restrict__ out_x, float* __restrict__ out_t, int N) {
    int w    = blockIdx.x * (blockDim.x >> 5) + (threadIdx.x >> 5);
    int lane = threadIdx.x & 31;
    if (w >= N) return;
    int p0 = g_off[w];
    int p1 = g_off[w + 1];

    const float s = 0.08838834764831845f;  // 1/sqrt(128)
    float4 qa = *(const float4*)(g_qa + (size_t)w * DD + lane * 4);
    float4 qb = *(const float4*)(g_qb + (size_t)w * DD + lane * 4);
    qa.x *= s; qa.y *= s; qa.z *= s; qa.w *= s;
    qb.x *= s; qb.y *= s; qb.z *= s; qb.w *= s;

    float stx = 0.f, sty = 0.f, stz = 0.f, stw = 0.f;
    float sxx = 0.f, sxy = 0.f, sxz = 0.f, sxw = 0.f;
    float da = 0.f, db = 0.f;

    for (int p = p0; p < p1; p++) {
        int j = g_scol[p];
        uint2 kau = *(const uint2*)(g_ka16 + (size_t)j * DD + lane * 4);
        uint2 kbu = *(const uint2*)(g_kb16 + (size_t)j * DD + lane * 4);
        float4 wt = *(const float4*)(g_wtp + (size_t)j * DD + lane * 4);
        float4 wx = *(const float4*)(g_wxp + (size_t)j * DD + lane * 4);

        float2 ka0 = __bfloat1622float2(*(__nv_bfloat162*)&kau.x);
        float2 ka1 = __bfloat1622float2(*(__nv_bfloat162*)&kau.y);
        float2 kb0 = __bfloat1622float2(*(__nv_bfloat162*)&kbu.x);
        float2 kb1 = __bfloat1622float2(*(__nv_bfloat162*)&kbu.y);

        float sa = qa.x * ka0.x + qa.y * ka0.y + qa.z * ka1.x + qa.w * ka1.y;
        float sb = qb.x * kb0.x + qb.y * kb0.y + qb.z * kb1.x + qb.w * kb1.y;
#pragma unroll
        for (int off = 16; off > 0; off >>= 1) {
            sa += __shfl_xor_sync(0xffffffffu, sa, off);
            sb += __shfl_xor_sync(0xffffffffu, sb, off);
        }
        float ea = __expf(sa);
        float eb = __expf(sb);

        stx = fmaf(ea, wt.x, stx);
        sty = fmaf(ea, wt.y, sty);
        stz = fmaf(ea, wt.z, stz);
        stw = fmaf(ea, wt.w, stw);
        sxx = fmaf(eb, wx.x, sxx);
        sxy = fmaf(eb, wx.y, sxy);
        sxz = fmaf(eb, wx.z, sxz);
        sxw = fmaf(eb, wx.w, sxw);
        da += ea;
        db += eb;
    }
    float ia = (da > 0.f) ? 1.f / da : 0.f;
    float ib = (db > 0.f) ? 1.f / db : 0.f;
    *(float4*)(out_t + (size_t)w * DD + lane * 4) =
        make_float4(stx * ia, sty * ia, stz * ia, stw * ia);
    *(float4*)(out_x + (size_t)w * DD + lane * 4) =
        make_float4(sxx * ib, sxy * ib, sxz * ib, sxw * ib);
}

// ---------------- launch ----------------
extern "C" void kernel_launch(void* const* d_in, const int* in_sizes, int n_in,
                              void* d_out, int out_size) {
    const float* x    = (const float*)d_in[0];
    const float* t    = (const float*)d_in[1];
    const int*   ei   = (const int*)d_in[2];
    const float* W_x  = (const float*)d_in[3];
    const float* W_t  = (const float*)d_in[4];
    const float* Qa_w = (const float*)d_in[5];
    const float* Qa_b = (const float*)d_in[6];
    const float* Ka_w = (const float*)d_in[7];
    const float* Ka_b = (const float*)d_in[8];
    const float* Qb_w = (const float*)d_in[9];
    const float* Qb_b = (const float*)d_in[10];
    const float* Kb_w = (const float*)d_in[11];
    const float* Kb_b = (const float*)d_in[12];

    const int N = in_sizes[0] / DD;
    const int E = in_sizes[2] / 2;
    const int* rows = ei;
    const int* cols = ei + E;

    float* out_x = (float*)d_out;
    float* out_t = out_x + (size_t)N * DD;

    // weight order: 0=Qa, 1=Ka, 2=W_t, 3=Qb, 4=Kb, 5=W_x (residuals for 2, 5)
    wsplit_kernel<<<6, 256>>>(Qa_w, Ka_w, W_t, Qb_w, Kb_w, W_x);

    // CSR
    zero_deg_kernel<<<(N + 255) / 256, 256>>>(N);
    count_deg_kernel<<<(E + 255) / 256, 256>>>(rows, E);
    const int G = (N + 1023) / 1024;
    scan1_kernel<<<G, 1024>>>(N);
    scan2_kernel<<<1, 32>>>(G, N, E);
    scan3_kernel<<<G, 1024>>>(N);
    scatter_kernel<<<(E + 255) / 256, 256>>>(rows, cols, E);

    // projections via bf16 m16n8k16 mma (message GEMM bf16x2-split)
    cudaFuncSetAttribute(proj_mma_kernel, cudaFuncAttributeMaxDynamicSharedMemorySize,
                         SMEM_BYTES);
    dim3 pg((N + 63) / 64, 2);
    proj_mma_kernel<<<pg, 256, SMEM_BYTES>>>(x, t, Qa_b, Ka_b, Qb_b, Kb_b, N);

    agg_kernel<<<(N + 7) / 8, 256>>>(out_x, out_t, N);
}

// round 8
// speedup vs baseline: 1.2295x; 1.0732x over previous
#include <cuda_runtime.h>
#include <cuda_bf16.h>
#include <cuda_fp16.h>
#include <stdint.h>
#include <stddef.h>

#define DD 128
#define NMAX 50176
#define EMAX 409600

// ---------------- device scratch ----------------
__device__ float g_qa[NMAX * DD];
__device__ float g_qb[NMAX * DD];
__device__ float g_wtp[NMAX * DD];
__device__ float g_wxp[NMAX * DD];
__device__ __nv_bfloat16 g_ka16[NMAX * DD];
__device__ __nv_bfloat16 g_kb16[NMAX * DD];
__device__ __half g_wh[6 * DD * DD];   // fp16-rounded weights
__device__ int   g_deg[NMAX];
__device__ int   g_off[NMAX + 1];
__device__ int   g_cur[NMAX];
__device__ int   g_scol[EMAX];
__device__ int   g_bsum[64];

// ---------------- cp.async helpers (portable, Ampere+) ----------------
__device__ __forceinline__ void cp_async16(uint32_t dst_smem, const void* src) {
    asm volatile("cp.async.cg.shared.global [%0], [%1], 16;" ::
                 "r"(dst_smem), "l"(src) : "memory");
}
#define CP_ASYNC_COMMIT() asm volatile("cp.async.commit_group;" ::: "memory")
#define CP_ASYNC_WAIT_ALL() asm volatile("cp.async.wait_group 0;" ::: "memory")

// ---------------- fp16 warp MMA (m16n8k16) ----------------
__device__ __forceinline__ void mma_f16(float* c, uint32_t a0, uint32_t a1,
                                        uint32_t a2, uint32_t a3,
                                        uint32_t b0, uint32_t b1) {
    asm volatile(
        "mma.sync.aligned.m16n8k16.row.col.f32.f16.f16.f32 "
        "{%0,%1,%2,%3}, {%4,%5,%6,%7}, {%8,%9}, {%0,%1,%2,%3};"
        : "+f"(c[0]), "+f"(c[1]), "+f"(c[2]), "+f"(c[3])
        : "r"(a0), "r"(a1), "r"(a2), "r"(a3), "r"(b0), "r"(b1));
}

// smem layout (fp16 elems): Ah[64][136], Al[64][136], B0[128][136], B1[128][136]
#define ROWE 136
#define AH_OFF 0
#define AL_OFF (64 * ROWE)
#define B0_OFF (2 * 64 * ROWE)
#define B1_OFF (B0_OFF + 128 * ROWE)
#define SMEM_ELEMS (B1_OFF + 128 * ROWE)
#define SMEM_BYTES (SMEM_ELEMS * 2)

// ---------------- fused: weight fp16 round + zero degree counters ----------------
__global__ void wsplit_zero_kernel(const float* __restrict__ W0,
                                   const float* __restrict__ W1,
                                   const float* __restrict__ W2,
                                   const float* __restrict__ W3,
                                   const float* __restrict__ W4,
                                   const float* __restrict__ W5, int N) {
    if (blockIdx.x < 6) {
        const float* W;
        switch (blockIdx.x) {
            case 0: W = W0; break;
            case 1: W = W1; break;
            case 2: W = W2; break;
            case 3: W = W3; break;
            case 4: W = W4; break;
            default: W = W5; break;
        }
        __half* dst = g_wh + blockIdx.x * (DD * DD);
        for (int i = threadIdx.x; i < DD * DD; i += 256)
            dst[i] = __float2half_rn(W[i]);
    } else {
        int i = (blockIdx.x - 6) * 256 + threadIdx.x;
        if (i < N) g_deg[i] = 0;
    }
}

// ---------------- GEMM inner pass: acc += A(16 rows) @ B(64 cols)^T ----------------
__device__ __forceinline__ void gemm_pass(float acc[8][4], const __half* Abase,
                                          const __half* Bbase, int warpM,
                                          int warpN, int g, int tg) {
    const __half* Ap = Abase + (warpM + g) * ROWE + 2 * tg;
    const __half* Bp = Bbase + (warpN + g) * ROWE + 2 * tg;
#pragma unroll
    for (int ks = 0; ks < 8; ks++) {
        const int k0 = ks * 16;
        uint32_t a0 = *(const uint32_t*)(Ap + k0);
        uint32_t a1 = *(const uint32_t*)(Ap + 8 * ROWE + k0);
        uint32_t a2 = *(const uint32_t*)(Ap + k0 + 8);
        uint32_t a3 = *(const uint32_t*)(Ap + 8 * ROWE + k0 + 8);
#pragma unroll
        for (int fn = 0; fn < 8; fn++) {
            const __half* bp = Bp + fn * 8 * ROWE + k0;
            uint32_t b0 = *(const uint32_t*)bp;
            uint32_t b1 = *(const uint32_t*)(bp + 8);
            mma_f16(acc[fn], a0, a1, a2, a3, b0, b1);
        }
    }
}

// ---------------- fused fp16 projection GEMM ----------------
// grid (ceil(N/64), 2). y=0: t -> {qa, ka16, wtp}; y=1: x -> {qb, kb16, wxp}.
// q: Ah*Wq (1 pass). k: Ah*Wk (1 pass). message: Ah*Wm + Al*Wm (2 passes).
__global__ void __launch_bounds__(256, 2)
proj_mma_kernel(const float* __restrict__ x, const float* __restrict__ t,
                const float* __restrict__ Qa_b, const float* __restrict__ Ka_b,
                const float* __restrict__ Qb_b, const float* __restrict__ Kb_b, int N) {
    extern __shared__ __half sm[];
    uint32_t sm_base = (uint32_t)__cvta_generic_to_shared(sm);

    const int tid  = threadIdx.x;
    const int wid  = tid >> 5;
    const int lane = tid & 31;
    const int y    = blockIdx.y;
    const int row0 = blockIdx.x * 64;

    const float* in = y ? x : t;
    const float* Bias[2];
    Bias[0] = y ? Qb_b : Qa_b;
    Bias[1] = y ? Kb_b : Ka_b;
    float* dst_q = y ? g_qb : g_qa;
    float* dst_w = y ? g_wxp : g_wtp;
    __nv_bfloat16* dst_k = y ? g_kb16 : g_ka16;
    const __half* wb = g_wh + (size_t)(y * 3) * (DD * DD);

    // ---- issue B0 <- W[0] ----
#pragma unroll
    for (int it = 0; it < 8; it++) {
        int c = tid + it * 256;
        int r = c >> 4, h8 = c & 15;
        uint32_t dst = sm_base + (uint32_t)((B0_OFF + r * ROWE + h8 * 8) * 2);
        cp_async16(dst, wb + (size_t)r * DD + h8 * 8);
    }
    CP_ASYNC_COMMIT();

    // ---- load A tile (64 x 128 fp32), split into Ah/Al fp16 ----
#pragma unroll
    for (int it = 0; it < 8; it++) {
        int c = tid + it * 256;
        int r = c >> 5, q4 = c & 31;
        int gr = row0 + r;
        float4 v = make_float4(0.f, 0.f, 0.f, 0.f);
        if (gr < N) v = *(const float4*)(in + (size_t)gr * DD + q4 * 4);
        __half h0 = __float2half_rn(v.x);
        __half h1 = __float2half_rn(v.y);
        __half h2 = __float2half_rn(v.z);
        __half h3 = __float2half_rn(v.w);
        __half l0 = __float2half_rn(v.x - __half2float(h0));
        __half l1 = __float2half_rn(v.y - __half2float(h1));
        __half l2 = __float2half_rn(v.z - __half2float(h2));
        __half l3 = __float2half_rn(v.w - __half2float(h3));
        __half* ah = sm + AH_OFF + r * ROWE + q4 * 4;
        __half* al = sm + AL_OFF + r * ROWE + q4 * 4;
        ah[0] = h0; ah[1] = h1; ah[2] = h2; ah[3] = h3;
        al[0] = l0; al[1] = l1; al[2] = l2; al[3] = l3;
    }
    CP_ASYNC_WAIT_ALL();
    __syncthreads();

    const int warpM = (wid >> 1) * 16;   // 0,16,32,48
    const int warpN = (wid & 1) * 64;    // 0,64
    const int g = lane >> 2;             // 0..7
    const int tg = lane & 3;             // 0..3
    const __half* Ahs = sm + AH_OFF;
    const __half* Als = sm + AL_OFF;
    const __half* Bs0 = sm + B0_OFF;
    const __half* Bs1 = sm + B1_OFF;

    // ---- prefetch B1 <- W[1], compute q on B0 ----
#pragma unroll
    for (int it = 0; it < 8; it++) {
        int c = tid + it * 256;
        int r = c >> 4, h8 = c & 15;
        uint32_t dst = sm_base + (uint32_t)((B1_OFF + r * ROWE + h8 * 8) * 2);
        cp_async16(dst, wb + (size_t)DD * DD + (size_t)r * DD + h8 * 8);
    }
    CP_ASYNC_COMMIT();

    float acc[8][4];
#pragma unroll
    for (int fn = 0; fn < 8; fn++)
#pragma unroll
        for (int i = 0; i < 4; i++) acc[fn][i] = 0.f;
    gemm_pass(acc, Ahs, Bs0, warpM, warpN, g, tg);

    // epilogue q -> fp32 + bias
    {
        const float* bias = Bias[0];
        int m_lo = row0 + warpM + g, m_hi = m_lo + 8;
#pragma unroll
        for (int fn = 0; fn < 8; fn++) {
            int col = warpN + fn * 8 + 2 * tg;
            float2 bv = *(const float2*)(bias + col);
            if (m_lo < N)
                *(float2*)(dst_q + (size_t)m_lo * DD + col) =
                    make_float2(acc[fn][0] + bv.x, acc[fn][1] + bv.y);
            if (m_hi < N)
                *(float2*)(dst_q + (size_t)m_hi * DD + col) =
                    make_float2(acc[fn][2] + bv.x, acc[fn][3] + bv.y);
        }
    }
    CP_ASYNC_WAIT_ALL();
    __syncthreads();

    // ---- prefetch B0 <- W[2] (message weight), compute k on B1 ----
#pragma unroll
    for (int it = 0; it < 8; it++) {
        int c = tid + it * 256;
        int r = c >> 4, h8 = c & 15;
        uint32_t dst = sm_base + (uint32_t)((B0_OFF + r * ROWE + h8 * 8) * 2);
        cp_async16(dst, wb + (size_t)2 * DD * DD + (size_t)r * DD + h8 * 8);
    }
    CP_ASYNC_COMMIT();

#pragma unroll
    for (int fn = 0; fn < 8; fn++)
#pragma unroll
        for (int i = 0; i < 4; i++) acc[fn][i] = 0.f;
    gemm_pass(acc, Ahs, Bs1, warpM, warpN, g, tg);

    // epilogue k -> bf16 + bias
    {
        const float* bias = Bias[1];
        int m_lo = row0 + warpM + g, m_hi = m_lo + 8;
#pragma unroll
        for (int fn = 0; fn < 8; fn++) {
            int col = warpN + fn * 8 + 2 * tg;
            float2 bv = *(const float2*)(bias + col);
            if (m_lo < N) {
                __nv_bfloat162 h = __floats2bfloat162_rn(acc[fn][0] + bv.x,
                                                         acc[fn][1] + bv.y);
                *(unsigned int*)(dst_k + (size_t)m_lo * DD + col) = *(unsigned int*)&h;
            }
            if (m_hi < N) {
                __nv_bfloat162 h = __floats2bfloat162_rn(acc[fn][2] + bv.x,
                                                         acc[fn][3] + bv.y);
                *(unsigned int*)(dst_k + (size_t)m_hi * DD + col) = *(unsigned int*)&h;
            }
        }
    }
    CP_ASYNC_WAIT_ALL();
    __syncthreads();

    // ---- message GEMM: Ah*Wm + Al*Wm on B0 ----
#pragma unroll
    for (int fn = 0; fn < 8; fn++)
#pragma unroll
        for (int i = 0; i < 4; i++) acc[fn][i] = 0.f;
    gemm_pass(acc, Ahs, Bs0, warpM, warpN, g, tg);
    gemm_pass(acc, Als, Bs0, warpM, warpN, g, tg);

    // epilogue message -> fp32, no bias
    {
        int m_lo = row0 + warpM + g, m_hi = m_lo + 8;
#pragma unroll
        for (int fn = 0; fn < 8; fn++) {
            int col = warpN + fn * 8 + 2 * tg;
            if (m_lo < N)
                *(float2*)(dst_w + (size_t)m_lo * DD + col) =
                    make_float2(acc[fn][0], acc[fn][1]);
            if (m_hi < N)
                *(float2*)(dst_w + (size_t)m_hi * DD + col) =
                    make_float2(acc[fn][2], acc[fn][3]);
        }
    }
}

// ---------------- CSR construction ----------------
__global__ void count_deg_kernel(const int* __restrict__ rows, int E) {
    int e = blockIdx.x * blockDim.x + threadIdx.x;
    if (e < E) atomicAdd(&g_deg[rows[e]], 1);
}

__global__ void scan1_kernel(int N) {
    __shared__ int wsum[32];
    int tid = threadIdx.x, lane = tid & 31, wid = tid >> 5;
    int i = blockIdx.x * 1024 + tid;
    int v = (i < N) ? g_deg[i] : 0;
    int s = v;
#pragma unroll
    for (int off = 1; off < 32; off <<= 1) {
        int u = __shfl_up_sync(0xffffffffu, s, off);
        if (lane >= off) s += u;
    }
    if (lane == 31) wsum[wid] = s;
    __syncthreads();
    if (wid == 0) {
        int ts = wsum[lane];
#pragma unroll
        for (int off = 1; off < 32; off <<= 1) {
            int u = __shfl_up_sync(0xffffffffu, ts, off);
            if (lane >= off) ts += u;
        }
        wsum[lane] = ts;
    }
    __syncthreads();
    int excl = (wid > 0 ? wsum[wid - 1] : 0) + (s - v);
    if (i < N) g_off[i] = excl;
    if (tid == 1023) g_bsum[blockIdx.x] = wsum[31];
}

// scan3 with inlined block-prefix: warp 0 sums g_bsum[0..blockIdx.x)
__global__ void scan3_kernel(int G, int N, int E) {
    __shared__ int pre_sh;
    int tid = threadIdx.x, lane = tid & 31, wid = tid >> 5;
    if (wid == 0) {
        int b = blockIdx.x;
        int v = 0;
        if (lane < b && lane < G) v += g_bsum[lane];
        if (32 + lane < b && 32 + lane < G) v += g_bsum[32 + lane];
#pragma unroll
        for (int off = 16; off > 0; off >>= 1)
            v += __shfl_xor_sync(0xffffffffu, v, off);
        if (lane == 0) pre_sh = v;
    }
    __syncthreads();
    int pre = pre_sh;
    int i = blockIdx.x * 1024 + tid;
    if (i < N) {
        int o = g_off[i] + pre;
        g_off[i] = o;
        g_cur[i] = o;
    }
    if (blockIdx.x == 0 && tid == 0) g_off[N] = E;
}

__global__ void scatter_kernel(const int* __restrict__ rows, const int* __restrict__ cols,
                               int E) {
    int e = blockIdx.x * blockDim.x + threadIdx.x;
    if (e < E) {
        int p = atomicAdd(&g_cur[rows[e]], 1);
        g_scol[p] = cols[e];
    }
}

// ---------------- fused scores + aggregation: one warp per dest node ----------------
__global__ void agg_kernel(float* __restrict__ out_x, float* __restrict__ out_t, int N) {
    int w    = blockIdx.x * (blockDim.x >> 5) + (threadIdx.x >> 5);
    int lane = threadIdx.x & 31;
    if (w >= N) return;
    int p0 = g_off[w];
    int p1 = g_off[w + 1];

    const float s = 0.08838834764831845f;  // 1/sqrt(128)
    float4 qa = *(const float4*)(g_qa + (size_t)w * DD + lane * 4);
    float4 qb = *(const float4*)(g_qb + (size_t)w * DD + lane * 4);
    qa.x *= s; qa.y *= s; qa.z *= s; qa.w *= s;
    qb.x *= s; qb.y *= s; qb.z *= s; qb.w *= s;

    float stx = 0.f, sty = 0.f, stz = 0.f, stw = 0.f;
    float sxx = 0.f, sxy = 0.f, sxz = 0.f, sxw = 0.f;
    float da = 0.f, db = 0.f;

    for (int p = p0; p < p1; p++) {
        int j = g_scol[p];
        uint2 kau = *(const uint2*)(g_ka16 + (size_t)j * DD + lane * 4);
        uint2 kbu = *(const uint2*)(g_kb16 + (size_t)j * DD + lane * 4);
        float4 wt = *(const float4*)(g_wtp + (size_t)j * DD + lane * 4);
        float4 wx = *(const float4*)(g_wxp + (size_t)j * DD + lane * 4);

        float2 ka0 = __bfloat1622float2(*(__nv_bfloat162*)&kau.x);
        float2 ka1 = __bfloat1622float2(*(__nv_bfloat162*)&kau.y);
        float2 kb0 = __bfloat1622float2(*(__nv_bfloat162*)&kbu.x);
        float2 kb1 = __bfloat1622float2(*(__nv_bfloat162*)&kbu.y);

        float sa = qa.x * ka0.x + qa.y * ka0.y + qa.z * ka1.x + qa.w * ka1.y;
        float sb = qb.x * kb0.x + qb.y * kb0.y + qb.z * kb1.x + qb.w * kb1.y;
#pragma unroll
        for (int off = 16; off > 0; off >>= 1) {
            sa += __shfl_xor_sync(0xffffffffu, sa, off);
            sb += __shfl_xor_sync(0xffffffffu, sb, off);
        }
        float ea = __expf(sa);
        float eb = __expf(sb);

        stx = fmaf(ea, wt.x, stx);
        sty = fmaf(ea, wt.y, sty);
        stz = fmaf(ea, wt.z, stz);
        stw = fmaf(ea, wt.w, stw);
        sxx = fmaf(eb, wx.x, sxx);
        sxy = fmaf(eb, wx.y, sxy);
        sxz = fmaf(eb, wx.z, sxz);
        sxw = fmaf(eb, wx.w, sxw);
        da += ea;
        db += eb;
    }
    float ia = (da > 0.f) ? 1.f / da : 0.f;
    float ib = (db > 0.f) ? 1.f / db : 0.f;
    *(float4*)(out_t + (size_t)w * DD + lane * 4) =
        make_float4(stx * ia, sty * ia, stz * ia, stw * ia);
    *(float4*)(out_x + (size_t)w * DD + lane * 4) =
        make_float4(sxx * ib, sxy * ib, sxz * ib, sxw * ib);
}

// ---------------- launch ----------------
extern "C" void kernel_launch(void* const* d_in, const int* in_sizes, int n_in,
                              void* d_out, int out_size) {
    const float* x    = (const float*)d_in[0];
    const float* t    = (const float*)d_in[1];
    const int*   ei   = (const int*)d_in[2];
    const float* W_x  = (const float*)d_in[3];
    const float* W_t  = (const float*)d_in[4];
    const float* Qa_w = (const float*)d_in[5];
    const float* Qa_b = (const float*)d_in[6];
    const float* Ka_w = (const float*)d_in[7];
    const float* Ka_b = (const float*)d_in[8];
    const float* Qb_w = (const float*)d_in[9];
    const float* Qb_b = (const float*)d_in[10];
    const float* Kb_w = (const float*)d_in[11];
    const float* Kb_b = (const float*)d_in[12];

    const int N = in_sizes[0] / DD;
    const int E = in_sizes[2] / 2;
    const int* rows = ei;
    const int* cols = ei + E;

    float* out_x = (float*)d_out;
    float* out_t = out_x + (size_t)N * DD;

    const int G = (N + 1023) / 1024;

    // launch order chosen so proj_mma_kernel is the 6th launch (ncu -s 5 -c 1)
    // weight order: 0=Qa, 1=Ka, 2=W_t, 3=Qb, 4=Kb, 5=W_x
    wsplit_zero_kernel<<<6 + (N + 255) / 256, 256>>>(Qa_w, Ka_w, W_t, Qb_w, Kb_w, W_x, N);
    count_deg_kernel<<<(E + 255) / 256, 256>>>(rows, E);
    scan1_kernel<<<G, 1024>>>(N);
    scan3_kernel<<<G, 1024>>>(G, N, E);
    scatter_kernel<<<(E + 255) / 256, 256>>>(rows, cols, E);

    cudaFuncSetAttribute(proj_mma_kernel, cudaFuncAttributeMaxDynamicSharedMemorySize,
                         SMEM_BYTES);
    dim3 pg((N + 63) / 64, 2);
    proj_mma_kernel<<<pg, 256, SMEM_BYTES>>>(x, t, Qa_b, Ka_b, Qb_b, Kb_b, N);

    agg_kernel<<<(N + 7) / 8, 256>>>(out_x, out_t, N);
}

// round 9
// speedup vs baseline: 1.4615x; 1.1887x over previous
#include <cuda_runtime.h>
#include <cuda_bf16.h>
#include <cuda_fp16.h>
#include <stdint.h>
#include <stddef.h>

#define DD 128
#define NMAX 50176
#define EMAX 409600

// ---------------- device scratch ----------------
__device__ float g_qa[NMAX * DD];
__device__ float g_qb[NMAX * DD];
__device__ __half g_wtp[NMAX * DD];     // fp16 messages
__device__ __half g_wxp[NMAX * DD];
__device__ __nv_bfloat16 g_ka16[NMAX * DD];
__device__ __nv_bfloat16 g_kb16[NMAX * DD];
__device__ __half g_wh[6 * DD * DD];    // fp16-rounded weights
__device__ int   g_deg[NMAX];
__device__ int   g_off[NMAX + 1];
__device__ int   g_cur[NMAX];
__device__ int   g_scol[EMAX];
__device__ int   g_bsum[64];

// ---------------- cp.async helpers (portable, Ampere+) ----------------
__device__ __forceinline__ void cp_async16(uint32_t dst_smem, const void* src) {
    asm volatile("cp.async.cg.shared.global [%0], [%1], 16;" ::
                 "r"(dst_smem), "l"(src) : "memory");
}
#define CP_ASYNC_COMMIT() asm volatile("cp.async.commit_group;" ::: "memory")
#define CP_ASYNC_WAIT_ALL() asm volatile("cp.async.wait_group 0;" ::: "memory")

// ---------------- fp16 warp MMA (m16n8k16) ----------------
__device__ __forceinline__ void mma_f16(float* c, uint32_t a0, uint32_t a1,
                                        uint32_t a2, uint32_t a3,
                                        uint32_t b0, uint32_t b1) {
    asm volatile(
        "mma.sync.aligned.m16n8k16.row.col.f32.f16.f16.f32 "
        "{%0,%1,%2,%3}, {%4,%5,%6,%7}, {%8,%9}, {%0,%1,%2,%3};"
        : "+f"(c[0]), "+f"(c[1]), "+f"(c[2]), "+f"(c[3])
        : "r"(a0), "r"(a1), "r"(a2), "r"(a3), "r"(b0), "r"(b1));
}

// smem layout (fp16 elems): Ah[64][136], Al[64][136], B0[128][136], B1[128][136]
#define ROWE 136
#define AH_OFF 0
#define AL_OFF (64 * ROWE)
#define B0_OFF (2 * 64 * ROWE)
#define B1_OFF (B0_OFF + 128 * ROWE)
#define SMEM_ELEMS (B1_OFF + 128 * ROWE)
#define SMEM_BYTES (SMEM_ELEMS * 2)

// ---------------- fused: weight fp16 round + zero degree counters ----------------
__global__ void wsplit_zero_kernel(const float* __restrict__ W0,
                                   const float* __restrict__ W1,
                                   const float* __restrict__ W2,
                                   const float* __restrict__ W3,
                                   const float* __restrict__ W4,
                                   const float* __restrict__ W5, int N) {
    if (blockIdx.x < 6) {
        const float* W;
        switch (blockIdx.x) {
            case 0: W = W0; break;
            case 1: W = W1; break;
            case 2: W = W2; break;
            case 3: W = W3; break;
            case 4: W = W4; break;
            default: W = W5; break;
        }
        __half* dst = g_wh + blockIdx.x * (DD * DD);
        for (int i = threadIdx.x; i < DD * DD; i += 256)
            dst[i] = __float2half_rn(W[i]);
    } else {
        int i = (blockIdx.x - 6) * 256 + threadIdx.x;
        if (i < N) g_deg[i] = 0;
    }
}

// ---------------- GEMM inner pass: acc += A(16 rows) @ B(64 cols)^T ----------------
__device__ __forceinline__ void gemm_pass(float acc[8][4], const __half* Abase,
                                          const __half* Bbase, int warpM,
                                          int warpN, int g, int tg) {
    const __half* Ap = Abase + (warpM + g) * ROWE + 2 * tg;
    const __half* Bp = Bbase + (warpN + g) * ROWE + 2 * tg;
#pragma unroll
    for (int ks = 0; ks < 8; ks++) {
        const int k0 = ks * 16;
        uint32_t a0 = *(const uint32_t*)(Ap + k0);
        uint32_t a1 = *(const uint32_t*)(Ap + 8 * ROWE + k0);
        uint32_t a2 = *(const uint32_t*)(Ap + k0 + 8);
        uint32_t a3 = *(const uint32_t*)(Ap + 8 * ROWE + k0 + 8);
#pragma unroll
        for (int fn = 0; fn < 8; fn++) {
            const __half* bp = Bp + fn * 8 * ROWE + k0;
            uint32_t b0 = *(const uint32_t*)bp;
            uint32_t b1 = *(const uint32_t*)(bp + 8);
            mma_f16(acc[fn], a0, a1, a2, a3, b0, b1);
        }
    }
}

// ---------------- fused fp16 projection GEMM ----------------
// grid (ceil(N/64), 2). y=0: t -> {qa, ka16, wtp}; y=1: x -> {qb, kb16, wxp}.
// q: Ah*Wq. k: Ah*Wk. message: Ah*Wm + Al*Wm (A-compensated).
__global__ void __launch_bounds__(256, 2)
proj_mma_kernel(const float* __restrict__ x, const float* __restrict__ t,
                const float* __restrict__ Qa_b, const float* __restrict__ Ka_b,
                const float* __restrict__ Qb_b, const float* __restrict__ Kb_b, int N) {
    extern __shared__ __half sm[];
    uint32_t sm_base = (uint32_t)__cvta_generic_to_shared(sm);

    const int tid  = threadIdx.x;
    const int wid  = tid >> 5;
    const int lane = tid & 31;
    const int y    = blockIdx.y;
    const int row0 = blockIdx.x * 64;

    const float* in = y ? x : t;
    const float* Bias[2];
    Bias[0] = y ? Qb_b : Qa_b;
    Bias[1] = y ? Kb_b : Ka_b;
    float* dst_q = y ? g_qb : g_qa;
    __half* dst_w = y ? g_wxp : g_wtp;
    __nv_bfloat16* dst_k = y ? g_kb16 : g_ka16;
    const __half* wb = g_wh + (size_t)(y * 3) * (DD * DD);

    // ---- issue B0 <- W[0] ----
#pragma unroll
    for (int it = 0; it < 8; it++) {
        int c = tid + it * 256;
        int r = c >> 4, h8 = c & 15;
        uint32_t dst = sm_base + (uint32_t)((B0_OFF + r * ROWE + h8 * 8) * 2);
        cp_async16(dst, wb + (size_t)r * DD + h8 * 8);
    }
    CP_ASYNC_COMMIT();

    // ---- load A tile (64 x 128 fp32), split into Ah/Al fp16 ----
#pragma unroll
    for (int it = 0; it < 8; it++) {
        int c = tid + it * 256;
        int r = c >> 5, q4 = c & 31;
        int gr = row0 + r;
        float4 v = make_float4(0.f, 0.f, 0.f, 0.f);
        if (gr < N) v = *(const float4*)(in + (size_t)gr * DD + q4 * 4);
        __half h0 = __float2half_rn(v.x);
        __half h1 = __float2half_rn(v.y);
        __half h2 = __float2half_rn(v.z);
        __half h3 = __float2half_rn(v.w);
        __half l0 = __float2half_rn(v.x - __half2float(h0));
        __half l1 = __float2half_rn(v.y - __half2float(h1));
        __half l2 = __float2half_rn(v.z - __half2float(h2));
        __half l3 = __float2half_rn(v.w - __half2float(h3));
        __half* ah = sm + AH_OFF + r * ROWE + q4 * 4;
        __half* al = sm + AL_OFF + r * ROWE + q4 * 4;
        ah[0] = h0; ah[1] = h1; ah[2] = h2; ah[3] = h3;
        al[0] = l0; al[1] = l1; al[2] = l2; al[3] = l3;
    }
    CP_ASYNC_WAIT_ALL();
    __syncthreads();

    const int warpM = (wid >> 1) * 16;   // 0,16,32,48
    const int warpN = (wid & 1) * 64;    // 0,64
    const int g = lane >> 2;             // 0..7
    const int tg = lane & 3;             // 0..3
    const __half* Ahs = sm + AH_OFF;
    const __half* Als = sm + AL_OFF;
    const __half* Bs0 = sm + B0_OFF;
    const __half* Bs1 = sm + B1_OFF;

    // ---- prefetch B1 <- W[1], compute q on B0 ----
#pragma unroll
    for (int it = 0; it < 8; it++) {
        int c = tid + it * 256;
        int r = c >> 4, h8 = c & 15;
        uint32_t dst = sm_base + (uint32_t)((B1_OFF + r * ROWE + h8 * 8) * 2);
        cp_async16(dst, wb + (size_t)DD * DD + (size_t)r * DD + h8 * 8);
    }
    CP_ASYNC_COMMIT();

    float acc[8][4];
#pragma unroll
    for (int fn = 0; fn < 8; fn++)
#pragma unroll
        for (int i = 0; i < 4; i++) acc[fn][i] = 0.f;
    gemm_pass(acc, Ahs, Bs0, warpM, warpN, g, tg);

    // epilogue q -> fp32 + bias
    {
        const float* bias = Bias[0];
        int m_lo = row0 + warpM + g, m_hi = m_lo + 8;
#pragma unroll
        for (int fn = 0; fn < 8; fn++) {
            int col = warpN + fn * 8 + 2 * tg;
            float2 bv = *(const float2*)(bias + col);
            if (m_lo < N)
                *(float2*)(dst_q + (size_t)m_lo * DD + col) =
                    make_float2(acc[fn][0] + bv.x, acc[fn][1] + bv.y);
            if (m_hi < N)
                *(float2*)(dst_q + (size_t)m_hi * DD + col) =
                    make_float2(acc[fn][2] + bv.x, acc[fn][3] + bv.y);
        }
    }
    CP_ASYNC_WAIT_ALL();
    __syncthreads();

    // ---- prefetch B0 <- W[2] (message weight), compute k on B1 ----
#pragma unroll
    for (int it = 0; it < 8; it++) {
        int c = tid + it * 256;
        int r = c >> 4, h8 = c & 15;
        uint32_t dst = sm_base + (uint32_t)((B0_OFF + r * ROWE + h8 * 8) * 2);
        cp_async16(dst, wb + (size_t)2 * DD * DD + (size_t)r * DD + h8 * 8);
    }
    CP_ASYNC_COMMIT();

#pragma unroll
    for (int fn = 0; fn < 8; fn++)
#pragma unroll
        for (int i = 0; i < 4; i++) acc[fn][i] = 0.f;
    gemm_pass(acc, Ahs, Bs1, warpM, warpN, g, tg);

    // epilogue k -> bf16 + bias
    {
        const float* bias = Bias[1];
        int m_lo = row0 + warpM + g, m_hi = m_lo + 8;
#pragma unroll
        for (int fn = 0; fn < 8; fn++) {
            int col = warpN + fn * 8 + 2 * tg;
            float2 bv = *(const float2*)(bias + col);
            if (m_lo < N) {
                __nv_bfloat162 h = __floats2bfloat162_rn(acc[fn][0] + bv.x,
                                                         acc[fn][1] + bv.y);
                *(unsigned int*)(dst_k + (size_t)m_lo * DD + col) = *(unsigned int*)&h;
            }
            if (m_hi < N) {
                __nv_bfloat162 h = __floats2bfloat162_rn(acc[fn][2] + bv.x,
                                                         acc[fn][3] + bv.y);
                *(unsigned int*)(dst_k + (size_t)m_hi * DD + col) = *(unsigned int*)&h;
            }
        }
    }
    CP_ASYNC_WAIT_ALL();
    __syncthreads();

    // ---- message GEMM: Ah*Wm + Al*Wm on B0 ----
#pragma unroll
    for (int fn = 0; fn < 8; fn++)
#pragma unroll
        for (int i = 0; i < 4; i++) acc[fn][i] = 0.f;
    gemm_pass(acc, Ahs, Bs0, warpM, warpN, g, tg);
    gemm_pass(acc, Als, Bs0, warpM, warpN, g, tg);

    // epilogue message -> fp16, no bias
    {
        int m_lo = row0 + warpM + g, m_hi = m_lo + 8;
#pragma unroll
        for (int fn = 0; fn < 8; fn++) {
            int col = warpN + fn * 8 + 2 * tg;
            if (m_lo < N) {
                __half2 h = __floats2half2_rn(acc[fn][0], acc[fn][1]);
                *(unsigned int*)(dst_w + (size_t)m_lo * DD + col) = *(unsigned int*)&h;
            }
            if (m_hi < N) {
                __half2 h = __floats2half2_rn(acc[fn][2], acc[fn][3]);
                *(unsigned int*)(dst_w + (size_t)m_hi * DD + col) = *(unsigned int*)&h;
            }
        }
    }
}

// ---------------- CSR construction ----------------
__global__ void count_deg_kernel(const int* __restrict__ rows, int E) {
    int e = blockIdx.x * blockDim.x + threadIdx.x;
    if (e < E) atomicAdd(&g_deg[rows[e]], 1);
}

__global__ void scan1_kernel(int N) {
    __shared__ int wsum[32];
    int tid = threadIdx.x, lane = tid & 31, wid = tid >> 5;
    int i = blockIdx.x * 1024 + tid;
    int v = (i < N) ? g_deg[i] : 0;
    int s = v;
#pragma unroll
    for (int off = 1; off < 32; off <<= 1) {
        int u = __shfl_up_sync(0xffffffffu, s, off);
        if (lane >= off) s += u;
    }
    if (lane == 31) wsum[wid] = s;
    __syncthreads();
    if (wid == 0) {
        int ts = wsum[lane];
#pragma unroll
        for (int off = 1; off < 32; off <<= 1) {
            int u = __shfl_up_sync(0xffffffffu, ts, off);
            if (lane >= off) ts += u;
        }
        wsum[lane] = ts;
    }
    __syncthreads();
    int excl = (wid > 0 ? wsum[wid - 1] : 0) + (s - v);
    if (i < N) g_off[i] = excl;
    if (tid == 1023) g_bsum[blockIdx.x] = wsum[31];
}

// scan3 with inlined block-prefix: warp 0 sums g_bsum[0..blockIdx.x)
__global__ void scan3_kernel(int G, int N, int E) {
    __shared__ int pre_sh;
    int tid = threadIdx.x, lane = tid & 31, wid = tid >> 5;
    if (wid == 0) {
        int b = blockIdx.x;
        int v = 0;
        if (lane < b && lane < G) v += g_bsum[lane];
        if (32 + lane < b && 32 + lane < G) v += g_bsum[32 + lane];
#pragma unroll
        for (int off = 16; off > 0; off >>= 1)
            v += __shfl_xor_sync(0xffffffffu, v, off);
        if (lane == 0) pre_sh = v;
    }
    __syncthreads();
    int pre = pre_sh;
    int i = blockIdx.x * 1024 + tid;
    if (i < N) {
        int o = g_off[i] + pre;
        g_off[i] = o;
        g_cur[i] = o;
    }
    if (blockIdx.x == 0 && tid == 0) g_off[N] = E;
}

__global__ void scatter_kernel(const int* __restrict__ rows, const int* __restrict__ cols,
                               int E) {
    int e = blockIdx.x * blockDim.x + threadIdx.x;
    if (e < E) {
        int p = atomicAdd(&g_cur[rows[e]], 1);
        g_scol[p] = cols[e];
    }
}

// ---------------- fused scores + aggregation: one warp per dest node ----------------
__global__ void agg_kernel(float* __restrict__ out_x, float* __restrict__ out_t, int N) {
    int w    = blockIdx.x * (blockDim.x >> 5) + (threadIdx.x >> 5);
    int lane = threadIdx.x & 31;
    if (w >= N) return;
    int p0 = g_off[w];
    int p1 = g_off[w + 1];

    const float s = 0.08838834764831845f;  // 1/sqrt(128)
    float4 qa = *(const float4*)(g_qa + (size_t)w * DD + lane * 4);
    float4 qb = *(const float4*)(g_qb + (size_t)w * DD + lane * 4);
    qa.x *= s; qa.y *= s; qa.z *= s; qa.w *= s;
    qb.x *= s; qb.y *= s; qb.z *= s; qb.w *= s;

    float stx = 0.f, sty = 0.f, stz = 0.f, stw = 0.f;
    float sxx = 0.f, sxy = 0.f, sxz = 0.f, sxw = 0.f;
    float da = 0.f, db = 0.f;

    for (int p = p0; p < p1; p++) {
        int j = g_scol[p];
        uint2 kau = *(const uint2*)(g_ka16 + (size_t)j * DD + lane * 4);
        uint2 kbu = *(const uint2*)(g_kb16 + (size_t)j * DD + lane * 4);
        uint2 wtu = *(const uint2*)(g_wtp + (size_t)j * DD + lane * 4);
        uint2 wxu = *(const uint2*)(g_wxp + (size_t)j * DD + lane * 4);

        float2 ka0 = __bfloat1622float2(*(__nv_bfloat162*)&kau.x);
        float2 ka1 = __bfloat1622float2(*(__nv_bfloat162*)&kau.y);
        float2 kb0 = __bfloat1622float2(*(__nv_bfloat162*)&kbu.x);
        float2 kb1 = __bfloat1622float2(*(__nv_bfloat162*)&kbu.y);

        float sa = qa.x * ka0.x + qa.y * ka0.y + qa.z * ka1.x + qa.w * ka1.y;
        float sb = qb.x * kb0.x + qb.y * kb0.y + qb.z * kb1.x + qb.w * kb1.y;
#pragma unroll
        for (int off = 16; off > 0; off >>= 1) {
            sa += __shfl_xor_sync(0xffffffffu, sa, off);
            sb += __shfl_xor_sync(0xffffffffu, sb, off);
        }
        float ea = __expf(sa);
        float eb = __expf(sb);

        float2 wt0 = __half22float2(*(__half2*)&wtu.x);
        float2 wt1 = __half22float2(*(__half2*)&wtu.y);
        float2 wx0 = __half22float2(*(__half2*)&wxu.x);
        float2 wx1 = __half22float2(*(__half2*)&wxu.y);

        stx = fmaf(ea, wt0.x, stx);
        sty = fmaf(ea, wt0.y, sty);
        stz = fmaf(ea, wt1.x, stz);
        stw = fmaf(ea, wt1.y, stw);
        sxx = fmaf(eb, wx0.x, sxx);
        sxy = fmaf(eb, wx0.y, sxy);
        sxz = fmaf(eb, wx1.x, sxz);
        sxw = fmaf(eb, wx1.y, sxw);
        da += ea;
        db += eb;
    }
    float ia = (da > 0.f) ? 1.f / da : 0.f;
    float ib = (db > 0.f) ? 1.f / db : 0.f;
    *(float4*)(out_t + (size_t)w * DD + lane * 4) =
        make_float4(stx * ia, sty * ia, stz * ia, stw * ia);
    *(float4*)(out_x + (size_t)w * DD + lane * 4) =
        make_float4(sxx * ib, sxy * ib, sxz * ib, sxw * ib);
}

// ---------------- launch ----------------
extern "C" void kernel_launch(void* const* d_in, const int* in_sizes, int n_in,
                              void* d_out, int out_size) {
    const float* x    = (const float*)d_in[0];
    const float* t    = (const float*)d_in[1];
    const int*   ei   = (const int*)d_in[2];
    const float* W_x  = (const float*)d_in[3];
    const float* W_t  = (const float*)d_in[4];
    const float* Qa_w = (const float*)d_in[5];
    const float* Qa_b = (const float*)d_in[6];
    const float* Ka_w = (const float*)d_in[7];
    const float* Ka_b = (const float*)d_in[8];
    const float* Qb_w = (const float*)d_in[9];
    const float* Qb_b = (const float*)d_in[10];
    const float* Kb_w = (const float*)d_in[11];
    const float* Kb_b = (const float*)d_in[12];

    const int N = in_sizes[0] / DD;
    const int E = in_sizes[2] / 2;
    const int* rows = ei;
    const int* cols = ei + E;

    float* out_x = (float*)d_out;
    float* out_t = out_x + (size_t)N * DD;

    const int G = (N + 1023) / 1024;

    // weight order: 0=Qa, 1=Ka, 2=W_t, 3=Qb, 4=Kb, 5=W_x
    wsplit_zero_kernel<<<6 + (N + 255) / 256, 256>>>(Qa_w, Ka_w, W_t, Qb_w, Kb_w, W_x, N);
    count_deg_kernel<<<(E + 255) / 256, 256>>>(rows, E);
    scan1_kernel<<<G, 1024>>>(N);
    scan3_kernel<<<G, 1024>>>(G, N, E);
    scatter_kernel<<<(E + 255) / 256, 256>>>(rows, cols, E);

    cudaFuncSetAttribute(proj_mma_kernel, cudaFuncAttributeMaxDynamicSharedMemorySize,
                         SMEM_BYTES);
    dim3 pg((N + 63) / 64, 2);
    proj_mma_kernel<<<pg, 256, SMEM_BYTES>>>(x, t, Qa_b, Ka_b, Qb_b, Kb_b, N);

    agg_kernel<<<(N + 7) / 8, 256>>>(out_x, out_t, N);
}